// round 16
// baseline (speedup 1.0000x reference)
#include <cuda_runtime.h>
#include <cuda_bf16.h>
#include <cstdint>
#include <cstddef>

// Problem dims: B=32, T=256, D=768, H=512, 4H=2048, N=25
// Output: d_out[0]=loss, d_out[1..]=logits[32,256,25]

// ---------------- scratch ----------------
__device__ __align__(16) float g_xz[2ull * 8192ull * 2048ull];   // [dir][t*32+b][2048]
__device__ __align__(16) float g_wT[2ull * 2048ull * 768ull];    // transposed tf32 weights
__device__ __align__(16) float g_x32[8192ull * 768ull];          // tf32-rounded embeddings
__device__ __align__(16) float g_hs[8192ull * 1024ull];          // [b*256+t][fwd 512 | bwd 512]
__device__ __align__(16) unsigned short g_h16[2 * 2 * 32 * 512]; // [dir][buf][b][u] bf16
__device__ float g_nll[32];
__device__ volatile int g_flags[128 * 32];                        // one 128B line per CTA
__device__ volatile int g_gen2;

#define SPIN_CAP (1 << 17)

__device__ __forceinline__ uint32_t smem_u32(const void* p) {
    uint32_t a;
    asm("{ .reg .u64 t; cvta.to.shared.u64 t, %1; cvt.u32.u64 %0, t; }" : "=r"(a) : "l"(p));
    return a;
}

__device__ __forceinline__ float to_tf32(float x) {
    uint32_t r;
    asm("cvt.rna.tf32.f32 %0, %1;" : "=r"(r) : "f"(x));
    return __uint_as_float(r);
}

__device__ __forceinline__ void mma_tf32(float c[4], const uint32_t a[4], const uint32_t b[2]) {
    asm volatile(
        "mma.sync.aligned.m16n8k8.row.col.f32.tf32.tf32.f32 "
        "{%0,%1,%2,%3}, {%4,%5,%6,%7}, {%8,%9}, {%0,%1,%2,%3};"
        : "+f"(c[0]), "+f"(c[1]), "+f"(c[2]), "+f"(c[3])
        : "r"(a[0]), "r"(a[1]), "r"(a[2]), "r"(a[3]),
          "r"(b[0]), "r"(b[1]));
}

__device__ __forceinline__ void mma_bf16(float c[4], const uint32_t a[4], const uint32_t b[2]) {
    asm volatile(
        "mma.sync.aligned.m16n8k16.row.col.f32.bf16.bf16.f32 "
        "{%0,%1,%2,%3}, {%4,%5,%6,%7}, {%8,%9}, {%0,%1,%2,%3};"
        : "+f"(c[0]), "+f"(c[1]), "+f"(c[2]), "+f"(c[3])
        : "r"(a[0]), "r"(a[1]), "r"(a[2]), "r"(a[3]),
          "r"(b[0]), "r"(b[1]));
}

__device__ __forceinline__ void ldsm_x4(uint32_t af[4], uint32_t addr) {
    asm volatile(
        "ldmatrix.sync.aligned.m8n8.x4.shared.b16 {%0,%1,%2,%3}, [%4];"
        : "=r"(af[0]), "=r"(af[1]), "=r"(af[2]), "=r"(af[3]) : "r"(addr));
}

__device__ __forceinline__ unsigned short f2bf(float x) {
    return __bfloat16_as_ushort(__float2bfloat16_rn(x));
}
__device__ __forceinline__ float bf2f(unsigned short u) {
    return __bfloat162float(__ushort_as_bfloat16(u));
}

__device__ __forceinline__ float fast_sigmoid(float x) {
    return __fdividef(1.f, 1.f + __expf(-x));
}
__device__ __forceinline__ float fast_tanh(float x) {
    float xc = fminf(fmaxf(x, -15.f), 15.f);
    float e = __expf(2.f * xc);
    return __fdividef(e - 1.f, e + 1.f);
}

// ================= K-1: profiling pad (keeps lstm in the ncu capture slot) ========
__global__ void prof_pad_kernel() { }

// ================= K0a: round x to tf32 =================
__global__ __launch_bounds__(256) void round_x_kernel(const float* __restrict__ x)
{
    size_t i = ((size_t)blockIdx.x * 256 + threadIdx.x) * 4;
    float4 v = *(const float4*)&x[i];
    v.x = to_tf32(v.x); v.y = to_tf32(v.y);
    v.z = to_tf32(v.z); v.w = to_tf32(v.w);
    *(float4*)&g_x32[i] = v;
}

// ================= K0b: transpose input weights -> g_wT[dir][n][k], tf32 ==========
__global__ __launch_bounds__(256) void transpose_w(
    const float* __restrict__ kf, const float* __restrict__ kb)
{
    __shared__ float t[32][33];
    const int dir = blockIdx.z;
    const float* __restrict__ w = dir ? kb : kf;
    const int kb0 = blockIdx.y * 32;
    const int nb0 = blockIdx.x * 32;
    const int tx = threadIdx.x & 31, ty = threadIdx.x >> 5;
#pragma unroll
    for (int r = 0; r < 32; r += 8)
        t[ty + r][tx] = w[(size_t)(kb0 + ty + r) * 2048 + nb0 + tx];
    __syncthreads();
#pragma unroll
    for (int r = 0; r < 32; r += 8)
        g_wT[((size_t)dir * 2048 + nb0 + ty + r) * 768 + kb0 + tx] = to_tf32(t[tx][ty + r]);
}

// ================= K1: xz = x @ K + b via mma.sync tf32 (pre-rounded inputs) ======
__global__ __launch_bounds__(256, 2) void xz_gemm_mma(
    const float* __restrict__ bf, const float* __restrict__ bb)
{
    __shared__ float As[2][128][20];
    __shared__ float Bs[2][16][136];

    const int m0 = blockIdx.y * 128;
    const int nb = blockIdx.x;            // 0..31
    const int dir = nb >> 4;
    const int n0 = (nb & 15) * 128;
    const float* __restrict__ x = g_x32;
    const float* __restrict__ wT = g_wT + (size_t)dir * 2048ull * 768ull;
    const float* __restrict__ bias = dir ? bb : bf;

    const int tid = threadIdx.x;
    const int warp = tid >> 5, lane = tid & 31;
    const int warpM = warp >> 1, warpN = warp & 1;
    const int mbase = warpM * 32, nbase = warpN * 64;
    const int gid = lane >> 2, tig = lane & 3;

    const int la_m = tid >> 1;
    const int la_k = (tid & 1) * 8;

    float c[2][8][4];
#pragma unroll
    for (int mi = 0; mi < 2; mi++)
#pragma unroll
        for (int ni = 0; ni < 8; ni++)
#pragma unroll
            for (int q = 0; q < 4; q++) c[mi][ni][q] = 0.f;

    {
        float4 a0 = *(const float4*)&x[(size_t)(m0 + la_m) * 768 + la_k];
        float4 a1 = *(const float4*)&x[(size_t)(m0 + la_m) * 768 + la_k + 4];
        *(float4*)&As[0][la_m][la_k] = a0;
        *(float4*)&As[0][la_m][la_k + 4] = a1;
        float4 b0 = *(const float4*)&wT[(size_t)(n0 + la_m) * 768 + la_k];
        float4 b1 = *(const float4*)&wT[(size_t)(n0 + la_m) * 768 + la_k + 4];
        Bs[0][la_k + 0][la_m] = b0.x; Bs[0][la_k + 1][la_m] = b0.y;
        Bs[0][la_k + 2][la_m] = b0.z; Bs[0][la_k + 3][la_m] = b0.w;
        Bs[0][la_k + 4][la_m] = b1.x; Bs[0][la_k + 5][la_m] = b1.y;
        Bs[0][la_k + 6][la_m] = b1.z; Bs[0][la_k + 7][la_m] = b1.w;
    }
    __syncthreads();

    int buf = 0;
    for (int kt = 0; kt < 48; kt++) {
        float4 pa0, pa1, pb0, pb1;
        if (kt < 47) {
            const int k0 = (kt + 1) * 16;
            pa0 = *(const float4*)&x[(size_t)(m0 + la_m) * 768 + k0 + la_k];
            pa1 = *(const float4*)&x[(size_t)(m0 + la_m) * 768 + k0 + la_k + 4];
            pb0 = *(const float4*)&wT[(size_t)(n0 + la_m) * 768 + k0 + la_k];
            pb1 = *(const float4*)&wT[(size_t)(n0 + la_m) * 768 + k0 + la_k + 4];
        }

#pragma unroll
        for (int ks = 0; ks < 2; ks++) {
            const int kk = ks * 8;
            uint32_t af[2][4];
#pragma unroll
            for (int mi = 0; mi < 2; mi++) {
                const int r = mbase + mi * 16 + gid;
                af[mi][0] = __float_as_uint(As[buf][r][kk + tig]);
                af[mi][1] = __float_as_uint(As[buf][r + 8][kk + tig]);
                af[mi][2] = __float_as_uint(As[buf][r][kk + tig + 4]);
                af[mi][3] = __float_as_uint(As[buf][r + 8][kk + tig + 4]);
            }
            uint32_t bfr[8][2];
#pragma unroll
            for (int ni = 0; ni < 8; ni++) {
                const int col = nbase + ni * 8 + gid;
                bfr[ni][0] = __float_as_uint(Bs[buf][kk + tig][col]);
                bfr[ni][1] = __float_as_uint(Bs[buf][kk + tig + 4][col]);
            }
#pragma unroll
            for (int mi = 0; mi < 2; mi++)
#pragma unroll
                for (int ni = 0; ni < 8; ni++)
                    mma_tf32(c[mi][ni], af[mi], bfr[ni]);
        }

        if (kt < 47) {
            const int nbuf = buf ^ 1;
            *(float4*)&As[nbuf][la_m][la_k] = pa0;
            *(float4*)&As[nbuf][la_m][la_k + 4] = pa1;
            Bs[nbuf][la_k + 0][la_m] = pb0.x; Bs[nbuf][la_k + 1][la_m] = pb0.y;
            Bs[nbuf][la_k + 2][la_m] = pb0.z; Bs[nbuf][la_k + 3][la_m] = pb0.w;
            Bs[nbuf][la_k + 4][la_m] = pb1.x; Bs[nbuf][la_k + 5][la_m] = pb1.y;
            Bs[nbuf][la_k + 6][la_m] = pb1.z; Bs[nbuf][la_k + 7][la_m] = pb1.w;
        }
        __syncthreads();
        buf ^= 1;
    }

    float* outp = g_xz + (size_t)dir * (8192ull * 2048ull);
#pragma unroll
    for (int mi = 0; mi < 2; mi++) {
        const int r0 = m0 + mbase + mi * 16 + gid;
        const int r1 = r0 + 8;
        const size_t o0 = (size_t)((r0 & 255) * 32 + (r0 >> 8)) * 2048;
        const size_t o1 = (size_t)((r1 & 255) * 32 + (r1 >> 8)) * 2048;
#pragma unroll
        for (int ni = 0; ni < 8; ni++) {
            const int cc = n0 + nbase + ni * 8 + tig * 2;
            float2 b2 = *(const float2*)&bias[cc];
            float2 v0 = { c[mi][ni][0] + b2.x, c[mi][ni][1] + b2.y };
            float2 v1 = { c[mi][ni][2] + b2.x, c[mi][ni][3] + b2.y };
            *(float2*)&outp[o0 + cc] = v0;
            *(float2*)&outp[o1 + cc] = v1;
        }
    }
}

// ================= K2: persistent BiLSTM recurrence (symmetric halves) ===========
// 128 CTAs (64/dir) x 256 threads. CTA owns 8 units = 32 gate cols = 4 n8 groups.
// Warp w: col-group cg = w&3, K-half kh2 = w>>2. Each half stages ITS OWN 256-col
// half of h (named barrier), runs its MMAs, publishes partials; each half then
// activates its own mi=kh2 cell row (1 cell/thread). Flags polled by tid 128..191.
__global__ __launch_bounds__(256, 1) void lstm_mma_kernel(
    const float* __restrict__ rf, const float* __restrict__ rb)
{
    const int bx  = blockIdx.x;       // 0..127
    const int dir = bx >> 6;
    const int u0  = (bx & 63) * 8;
    const int tid = threadIdx.x;
    const int warp = tid >> 5, lane = tid & 31;
    const int gid = lane >> 2, tig = lane & 3;
    const int cg  = warp & 3;         // col group (n8)
    const int kh2 = warp >> 2;        // K half: 0 or 1
    const int dirbase = dir * 64;

    extern __shared__ char dsm[];
    unsigned short* h_s = (unsigned short*)dsm;    // [32][520] halves (LDSM conflict-free)
    float* red = (float*)(dsm + 66560);            // [2 halves][4][32][8]

    // ---- resident W fragments: warp covers cols [cg*8,+8), K [kh2*256,+256) ----
    const float* __restrict__ rec = dir ? rb : rf;
    const int colc = cg * 8 + gid;
    const int colg = (colc & 3) * 512 + u0 + (colc >> 2);
    uint32_t bw_hi[16][2], bw_lo[16][2];
#pragma unroll
    for (int kc = 0; kc < 16; kc++) {
#pragma unroll
        for (int q = 0; q < 2; q++) {
            const int ka = kh2 * 256 + kc * 16 + 2 * tig + q * 8;
            float w0 = rec[(size_t)ka * 2048 + colg];
            float w1 = rec[(size_t)(ka + 1) * 2048 + colg];
            unsigned short h0 = f2bf(w0), h1 = f2bf(w1);
            unsigned short l0 = f2bf(w0 - bf2f(h0)), l1 = f2bf(w1 - bf2f(h1));
            bw_hi[kc][q] = (uint32_t)h0 | ((uint32_t)h1 << 16);
            bw_lo[kc][q] = (uint32_t)l0 | ((uint32_t)l1 << 16);
        }
    }

    // LDSM per-lane base addresses (bytes) for mi = 0,1
    const int lrow = lane & 15;
    const int lkof = ((lane >> 4) & 1) * 8;
    uint32_t ldsm_base[2];
#pragma unroll
    for (int mi = 0; mi < 2; mi++)
        ldsm_base[mi] = smem_u32(h_s) +
            2u * (uint32_t)((mi * 16 + lrow) * 520 + kh2 * 256 + lkof);

    // this thread's cell: mi = kh2
    const int uu = u0 + cg * 2 + (tig >> 1);
    const int b_cell = kh2 * 16 + gid + (tig & 1) * 8;

    const float* __restrict__ xz = g_xz + (size_t)dir * (8192ull * 2048ull);
    unsigned short* hbase = g_h16 + dir * 32768;
    float c_st = 0.f;
    const int base = g_flags[bx * 32];
    const int ht = tid & 127;         // index within half
    __syncthreads();

    // prefetch xz for t=0
    float z[4];
    {
        const int txi0 = dir ? 255 : 0;
        const float* slab = xz + ((size_t)txi0 * 32 + b_cell) * 2048 + uu;
#pragma unroll
        for (int g = 0; g < 4; g++) z[g] = slab[g * 512];
    }

    for (int t = 0; t < 256; t++) {
        const int txi = dir ? (255 - t) : t;

        if (t > 0) {
            // each half stages its OWN 256-col half of h (16KB), then named-bars
            const uint4* h4 = (const uint4*)(hbase + ((t + 1) & 1) * 16384);
#pragma unroll
            for (int j = 0; j < 8; j++) {
                int i = ht + j * 128;              // 0..1023
                int b = i >> 5, kq = kh2 * 32 + (i & 31);
                uint4 v = __ldcg(&h4[b * 64 + kq]);
                *(uint4*)&h_s[b * 520 + kq * 8] = v;
            }
            asm volatile("bar.sync %0, 128;" :: "r"(1 + kh2) : "memory");

            float c[2][4];
#pragma unroll
            for (int mi = 0; mi < 2; mi++)
#pragma unroll
                for (int q = 0; q < 4; q++) c[mi][q] = 0.f;

#pragma unroll
            for (int kc = 0; kc < 16; kc++) {
#pragma unroll
                for (int mi = 0; mi < 2; mi++) {
                    uint32_t af[4];
                    ldsm_x4(af, ldsm_base[mi] + kc * 32);
                    mma_bf16(c[mi], af, bw_hi[kc]);
                    mma_bf16(c[mi], af, bw_lo[kc]);
                }
            }

            // both halves publish partials
            {
                float* rp = red + ((kh2 * 128) + cg * 32 + lane) * 8;
                *(float4*)&rp[0] = make_float4(c[0][0], c[0][1], c[0][2], c[0][3]);
                *(float4*)&rp[4] = make_float4(c[1][0], c[1][1], c[1][2], c[1][3]);
            }
            __syncthreads();

            // complete C for own mi=kh2: own partial + other half's partial
            {
                const float* ro = red + (((1 - kh2) * 128) + cg * 32 + lane) * 8 + kh2 * 4;
                float4 p = *(const float4*)ro;
                float cc0 = c[kh2][0] + p.x;
                float cc1 = c[kh2][1] + p.y;
                float cc2 = c[kh2][2] + p.z;
                float cc3 = c[kh2][3] + p.w;

                float s0 = __shfl_xor_sync(0xffffffffu, cc0, 1);
                float s1 = __shfl_xor_sync(0xffffffffu, cc1, 1);
                float s2 = __shfl_xor_sync(0xffffffffu, cc2, 1);
                float s3 = __shfl_xor_sync(0xffffffffu, cc3, 1);
                if ((tig & 1) == 0) {
                    z[0] += cc0; z[1] += cc1; z[2] += s0; z[3] += s1;
                } else {
                    z[0] += s2;  z[1] += s3;  z[2] += cc2; z[3] += cc3;
                }
            }
        }

        // activation: single cell per thread
        float ig = fast_sigmoid(z[0]);
        float fg = fast_sigmoid(z[1]);
        float gg = fast_tanh(z[2]);
        float og = fast_sigmoid(z[3]);
        c_st = fmaf(fg, c_st, ig * gg);
        float hout = og * fast_tanh(c_st);

        if (t < 255) {
            hbase[(t & 1) * 16384 + b_cell * 512 + uu] = f2bf(hout);
            __threadfence();
            __syncthreads();
            if (tid == 0) g_flags[bx * 32] = base + t + 1;
        }

        // non-critical: output store + next xz prefetch (hidden under barrier wait)
        g_hs[((size_t)b_cell * 256 + txi) * 1024 + dir * 512 + uu] = hout;
        if (t < 255) {
            const int txn = dir ? (255 - (t + 1)) : (t + 1);
            const float* slab = xz + ((size_t)txn * 32 + b_cell) * 2048 + uu;
#pragma unroll
            for (int g = 0; g < 4; g++) z[g] = slab[g * 512];

            // acquire: poll on tid 128..191 (kh2=1 warps)
            if (tid >= 128 && tid < 192) {
                int spins = 0;
                const int target = base + t + 1;
                while (g_flags[(dirbase + (tid - 128)) * 32] < target) {
                    if (++spins > SPIN_CAP) break;
                }
            }
            __syncthreads();
            __threadfence();
        }
    }
}

// ================= K3: dense + SELU (2 rows per warp) ============================
__global__ __launch_bounds__(256) void dense_kernel(
    const float* __restrict__ W, const float* __restrict__ bias, float* __restrict__ logits)
{
    int wpair = (blockIdx.x * blockDim.x + threadIdx.x) >> 5;   // 0..4095
    int lane = threadIdx.x & 31;
    if (wpair >= 4096) return;
    const size_t r0 = (size_t)wpair * 2;
    const float4* h0 = (const float4*)(g_hs + r0 * 1024);
    const float4* h1 = (const float4*)(g_hs + (r0 + 1) * 1024);
    float acc0 = 0.f, acc1 = 0.f;
#pragma unroll 4
    for (int k4 = 0; k4 < 256; k4++) {
        float4 a = h0[k4];
        float4 b = h1[k4];
        int k = k4 * 4;
        if (lane < 25) {
            float w0 = W[(k + 0) * 25 + lane];
            float w1 = W[(k + 1) * 25 + lane];
            float w2 = W[(k + 2) * 25 + lane];
            float w3 = W[(k + 3) * 25 + lane];
            acc0 = fmaf(a.x, w0, acc0); acc1 = fmaf(b.x, w0, acc1);
            acc0 = fmaf(a.y, w1, acc0); acc1 = fmaf(b.y, w1, acc1);
            acc0 = fmaf(a.z, w2, acc0); acc1 = fmaf(b.z, w2, acc1);
            acc0 = fmaf(a.w, w3, acc0); acc1 = fmaf(b.w, w3, acc1);
        }
    }
    if (lane < 25) {
        float bi = bias[lane];
        float y0 = acc0 + bi, y1 = acc1 + bi;
        y0 = 1.0507009873554805f * (y0 > 0.f ? y0 : 1.6732632423543772f * (__expf(y0) - 1.f));
        y1 = 1.0507009873554805f * (y1 > 0.f ? y1 : 1.6732632423543772f * (__expf(y1) - 1.f));
        logits[r0 * 25 + lane] = y0;
        logits[(r0 + 1) * 25 + lane] = y1;
    }
}

// ================= K4: CRF NLL per batch (register alpha + shfl) =================
__global__ __launch_bounds__(32) void crf_kernel(
    const float* __restrict__ logits, const int* __restrict__ tags,
    const int* __restrict__ lens, const float* __restrict__ trans)
{
    const int b = blockIdx.x;
    const int j = threadIdx.x;
    __shared__ float tr[625];
    for (int i = j; i < 625; i += 32) tr[i] = trans[i];
    int len = lens[b];
    if (len < 1) len = 1;
    if (len > 256) len = 256;
    const float* lg = logits + (size_t)b * 256 * 25;
    __syncthreads();

    float a = (j < 25) ? lg[j] : -1e30f;
    for (int t = 1; t < 256; t++) {
        float m = -1e30f;
        float v[25];
#pragma unroll
        for (int i = 0; i < 25; i++) {
            v[i] = __shfl_sync(0xffffffffu, a, i) + tr[i * 25 + j];
            m = fmaxf(m, v[i]);
        }
        float s = 0.f;
#pragma unroll
        for (int i = 0; i < 25; i++) s += __expf(v[i] - m);
        float nv = m + __logf(s) + lg[t * 25 + j];
        if (j < 25 && t < len) a = nv;
    }

    float m = a;
#pragma unroll
    for (int o = 16; o > 0; o >>= 1) m = fmaxf(m, __shfl_xor_sync(0xffffffffu, m, o));
    float e = (j < 25) ? __expf(a - m) : 0.f;
#pragma unroll
    for (int o = 16; o > 0; o >>= 1) e += __shfl_xor_sync(0xffffffffu, e, o);
    float logz = m + __logf(e);

    const int* tg = tags + (size_t)b * 256;
    float us = 0.f, bs = 0.f;
    for (int t = j; t < 256; t += 32) {
        if (t < len) {
            us += lg[t * 25 + tg[t]];
            if (t >= 1) bs += tr[tg[t - 1] * 25 + tg[t]];
        }
    }
#pragma unroll
    for (int o = 16; o > 0; o >>= 1) {
        us += __shfl_xor_sync(0xffffffffu, us, o);
        bs += __shfl_xor_sync(0xffffffffu, bs, o);
    }
    if (j == 0) g_nll[b] = -(us + bs - logz);
}

// ================= K5: loss = mean(nll) =================
__global__ __launch_bounds__(32) void loss_kernel(float* __restrict__ out)
{
    float v = g_nll[threadIdx.x];
#pragma unroll
    for (int o = 16; o > 0; o >>= 1) v += __shfl_xor_sync(0xffffffffu, v, o);
    if (threadIdx.x == 0) out[0] = v * (1.f / 32.f);
}

// ================= launcher =================
extern "C" void kernel_launch(void* const* d_in, const int* in_sizes, int n_in,
                              void* d_out, int out_size)
{
    const float* x     = (const float*)d_in[0];
    const int*   tags  = (const int*)d_in[1];
    const int*   lens  = (const int*)d_in[2];
    const float* kf    = (const float*)d_in[3];
    const float* rf    = (const float*)d_in[4];
    const float* bf    = (const float*)d_in[5];
    const float* kb    = (const float*)d_in[6];
    const float* rb    = (const float*)d_in[7];
    const float* bb    = (const float*)d_in[8];
    const float* dw    = (const float*)d_in[9];
    const float* db    = (const float*)d_in[10];
    const float* trans = (const float*)d_in[11];
    float* out = (float*)d_out;

    (void)in_sizes; (void)n_in; (void)out_size;

    // K-1: profiling pad (keeps lstm_mma_kernel in the ncu capture slot)
    prof_pad_kernel<<<1, 32>>>();

    // K0a: pre-round x to tf32 (8192*768/1024 = 6144 blocks)
    round_x_kernel<<<6144, 256>>>(x);

    // K0b: transpose + round input weights
    dim3 gt(64, 24, 2);
    transpose_w<<<gt, 256>>>(kf, kb);

    // K1: tf32 mma.sync input projections (pre-rounded operands)
    dim3 g1(32, 64);
    xz_gemm_mma<<<g1, 256>>>(bf, bb);

    // K2: persistent recurrence (symmetric halves)
    const int k2_smem = 66560 + 8192;   // h_s [32][520] bf16 + red [2][4][32][8] f32
    cudaFuncSetAttribute(lstm_mma_kernel, cudaFuncAttributeMaxDynamicSharedMemorySize, k2_smem);
    lstm_mma_kernel<<<128, 256, k2_smem>>>(rf, rb);

    // K3: dense + SELU (2 rows per warp)
    dense_kernel<<<512, 256>>>(dw, db, out + 1);

    // K4: CRF per batch
    crf_kernel<<<32, 32>>>(out + 1, tags, lens, trans);

    // K5: mean loss
    loss_kernel<<<1, 32>>>(out);
}

// round 17
// speedup vs baseline: 1.1057x; 1.1057x over previous
#include <cuda_runtime.h>
#include <cuda_bf16.h>
#include <cstdint>
#include <cstddef>

// Problem dims: B=32, T=256, D=768, H=512, 4H=2048, N=25
// Output: d_out[0]=loss, d_out[1..]=logits[32,256,25]

// ---------------- scratch ----------------
__device__ __align__(16) float g_xz[2ull * 8192ull * 2048ull];   // [dir][t*32+b][2048]
__device__ __align__(16) float g_wT[2ull * 2048ull * 768ull];    // transposed tf32 weights
__device__ __align__(16) float g_x32[8192ull * 768ull];          // tf32-rounded embeddings
__device__ __align__(16) float g_hs[8192ull * 1024ull];          // [b*256+t][fwd 512 | bwd 512]
__device__ __align__(16) unsigned short g_h16[2 * 2 * 32 * 512]; // [dir][buf][b][u] bf16
__device__ float g_nll[32];
__device__ volatile int g_flags[128 * 32];                        // one 128B line per CTA
__device__ volatile int g_gen2;

#define SPIN_CAP (1 << 17)

__device__ __forceinline__ uint32_t smem_u32(const void* p) {
    uint32_t a;
    asm("{ .reg .u64 t; cvta.to.shared.u64 t, %1; cvt.u32.u64 %0, t; }" : "=r"(a) : "l"(p));
    return a;
}

__device__ __forceinline__ float to_tf32(float x) {
    uint32_t r;
    asm("cvt.rna.tf32.f32 %0, %1;" : "=r"(r) : "f"(x));
    return __uint_as_float(r);
}

__device__ __forceinline__ void mma_tf32(float c[4], const uint32_t a[4], const uint32_t b[2]) {
    asm volatile(
        "mma.sync.aligned.m16n8k8.row.col.f32.tf32.tf32.f32 "
        "{%0,%1,%2,%3}, {%4,%5,%6,%7}, {%8,%9}, {%0,%1,%2,%3};"
        : "+f"(c[0]), "+f"(c[1]), "+f"(c[2]), "+f"(c[3])
        : "r"(a[0]), "r"(a[1]), "r"(a[2]), "r"(a[3]),
          "r"(b[0]), "r"(b[1]));
}

__device__ __forceinline__ void mma_bf16(float c[4], const uint32_t a[4], const uint32_t b[2]) {
    asm volatile(
        "mma.sync.aligned.m16n8k16.row.col.f32.bf16.bf16.f32 "
        "{%0,%1,%2,%3}, {%4,%5,%6,%7}, {%8,%9}, {%0,%1,%2,%3};"
        : "+f"(c[0]), "+f"(c[1]), "+f"(c[2]), "+f"(c[3])
        : "r"(a[0]), "r"(a[1]), "r"(a[2]), "r"(a[3]),
          "r"(b[0]), "r"(b[1]));
}

__device__ __forceinline__ void ldsm_x4(uint32_t af[4], uint32_t addr) {
    asm volatile(
        "ldmatrix.sync.aligned.m8n8.x4.shared.b16 {%0,%1,%2,%3}, [%4];"
        : "=r"(af[0]), "=r"(af[1]), "=r"(af[2]), "=r"(af[3]) : "r"(addr));
}

__device__ __forceinline__ unsigned short f2bf(float x) {
    return __bfloat16_as_ushort(__float2bfloat16_rn(x));
}
__device__ __forceinline__ float bf2f(unsigned short u) {
    return __bfloat162float(__ushort_as_bfloat16(u));
}

__device__ __forceinline__ float fast_sigmoid(float x) {
    return __fdividef(1.f, 1.f + __expf(-x));
}
__device__ __forceinline__ float fast_tanh(float x) {
    float xc = fminf(fmaxf(x, -15.f), 15.f);
    float e = __expf(2.f * xc);
    return __fdividef(e - 1.f, e + 1.f);
}

// ================= K-1: profiling pad ============================================
__global__ void prof_pad_kernel() { }

// ================= K0a: round x to tf32 =================
__global__ __launch_bounds__(256) void round_x_kernel(const float* __restrict__ x)
{
    size_t i = ((size_t)blockIdx.x * 256 + threadIdx.x) * 4;
    float4 v = *(const float4*)&x[i];
    v.x = to_tf32(v.x); v.y = to_tf32(v.y);
    v.z = to_tf32(v.z); v.w = to_tf32(v.w);
    *(float4*)&g_x32[i] = v;
}

// ================= K0b: transpose input weights -> g_wT[dir][n][k], tf32 ==========
__global__ __launch_bounds__(256) void transpose_w(
    const float* __restrict__ kf, const float* __restrict__ kb)
{
    __shared__ float t[32][33];
    const int dir = blockIdx.z;
    const float* __restrict__ w = dir ? kb : kf;
    const int kb0 = blockIdx.y * 32;
    const int nb0 = blockIdx.x * 32;
    const int tx = threadIdx.x & 31, ty = threadIdx.x >> 5;
#pragma unroll
    for (int r = 0; r < 32; r += 8)
        t[ty + r][tx] = w[(size_t)(kb0 + ty + r) * 2048 + nb0 + tx];
    __syncthreads();
#pragma unroll
    for (int r = 0; r < 32; r += 8)
        g_wT[((size_t)dir * 2048 + nb0 + ty + r) * 768 + kb0 + tx] = to_tf32(t[tx][ty + r]);
}

// ================= K1: xz = x @ K + b via mma.sync tf32 ===========================
// Both A and B tiles K-major [128][20] in smem: float4 stages, conflict-free frags.
__global__ __launch_bounds__(256, 2) void xz_gemm_mma(
    const float* __restrict__ bf, const float* __restrict__ bb)
{
    __shared__ float As[2][128][20];
    __shared__ float Bs[2][128][20];

    const int m0 = blockIdx.y * 128;
    const int nb = blockIdx.x;            // 0..31
    const int dir = nb >> 4;
    const int n0 = (nb & 15) * 128;
    const float* __restrict__ x = g_x32;
    const float* __restrict__ wT = g_wT + (size_t)dir * 2048ull * 768ull;
    const float* __restrict__ bias = dir ? bb : bf;

    const int tid = threadIdx.x;
    const int warp = tid >> 5, lane = tid & 31;
    const int warpM = warp >> 1, warpN = warp & 1;
    const int mbase = warpM * 32, nbase = warpN * 64;
    const int gid = lane >> 2, tig = lane & 3;

    const int la_m = tid >> 1;
    const int la_k = (tid & 1) * 8;

    float c[2][8][4];
#pragma unroll
    for (int mi = 0; mi < 2; mi++)
#pragma unroll
        for (int ni = 0; ni < 8; ni++)
#pragma unroll
            for (int q = 0; q < 4; q++) c[mi][ni][q] = 0.f;

    {
        *(float4*)&As[0][la_m][la_k]     = *(const float4*)&x[(size_t)(m0 + la_m) * 768 + la_k];
        *(float4*)&As[0][la_m][la_k + 4] = *(const float4*)&x[(size_t)(m0 + la_m) * 768 + la_k + 4];
        *(float4*)&Bs[0][la_m][la_k]     = *(const float4*)&wT[(size_t)(n0 + la_m) * 768 + la_k];
        *(float4*)&Bs[0][la_m][la_k + 4] = *(const float4*)&wT[(size_t)(n0 + la_m) * 768 + la_k + 4];
    }
    __syncthreads();

    int buf = 0;
    for (int kt = 0; kt < 48; kt++) {
        float4 pa0, pa1, pb0, pb1;
        if (kt < 47) {
            const int k0 = (kt + 1) * 16;
            pa0 = *(const float4*)&x[(size_t)(m0 + la_m) * 768 + k0 + la_k];
            pa1 = *(const float4*)&x[(size_t)(m0 + la_m) * 768 + k0 + la_k + 4];
            pb0 = *(const float4*)&wT[(size_t)(n0 + la_m) * 768 + k0 + la_k];
            pb1 = *(const float4*)&wT[(size_t)(n0 + la_m) * 768 + k0 + la_k + 4];
        }

#pragma unroll
        for (int ks = 0; ks < 2; ks++) {
            const int kk = ks * 8;
            uint32_t af[2][4];
#pragma unroll
            for (int mi = 0; mi < 2; mi++) {
                const int r = mbase + mi * 16 + gid;
                af[mi][0] = __float_as_uint(As[buf][r][kk + tig]);
                af[mi][1] = __float_as_uint(As[buf][r + 8][kk + tig]);
                af[mi][2] = __float_as_uint(As[buf][r][kk + tig + 4]);
                af[mi][3] = __float_as_uint(As[buf][r + 8][kk + tig + 4]);
            }
            uint32_t bfr[8][2];
#pragma unroll
            for (int ni = 0; ni < 8; ni++) {
                const int col = nbase + ni * 8 + gid;
                bfr[ni][0] = __float_as_uint(Bs[buf][col][kk + tig]);
                bfr[ni][1] = __float_as_uint(Bs[buf][col][kk + tig + 4]);
            }
#pragma unroll
            for (int mi = 0; mi < 2; mi++)
#pragma unroll
                for (int ni = 0; ni < 8; ni++)
                    mma_tf32(c[mi][ni], af[mi], bfr[ni]);
        }

        if (kt < 47) {
            const int nbuf = buf ^ 1;
            *(float4*)&As[nbuf][la_m][la_k]     = pa0;
            *(float4*)&As[nbuf][la_m][la_k + 4] = pa1;
            *(float4*)&Bs[nbuf][la_m][la_k]     = pb0;
            *(float4*)&Bs[nbuf][la_m][la_k + 4] = pb1;
        }
        __syncthreads();
        buf ^= 1;
    }

    float* outp = g_xz + (size_t)dir * (8192ull * 2048ull);
#pragma unroll
    for (int mi = 0; mi < 2; mi++) {
        const int r0 = m0 + mbase + mi * 16 + gid;
        const int r1 = r0 + 8;
        const size_t o0 = (size_t)((r0 & 255) * 32 + (r0 >> 8)) * 2048;
        const size_t o1 = (size_t)((r1 & 255) * 32 + (r1 >> 8)) * 2048;
#pragma unroll
        for (int ni = 0; ni < 8; ni++) {
            const int cc = n0 + nbase + ni * 8 + tig * 2;
            float2 b2 = *(const float2*)&bias[cc];
            float2 v0 = { c[mi][ni][0] + b2.x, c[mi][ni][1] + b2.y };
            float2 v1 = { c[mi][ni][2] + b2.x, c[mi][ni][3] + b2.y };
            *(float2*)&outp[o0 + cc] = v0;
            *(float2*)&outp[o1 + cc] = v1;
        }
    }
}

// ================= K2: persistent BiLSTM recurrence (R12/R15 proven config) =======
// 128 CTAs (64/dir) x 256 threads (8 warps). CTA owns 8 units = 32 gate cols = 4 n8 groups.
// Warp w: col-group cg = w&3, K-half kh2 = w>>2 (256 each). ONE pair-reduce completes C.
// A-frags via ldmatrix.x4 from staged smem h; B-frags (W hi/lo bf16) resident in registers.
// Flags polled by kh2=1 warps (tid 128..191), idle after publishing partials.
__global__ __launch_bounds__(256, 1) void lstm_mma_kernel(
    const float* __restrict__ rf, const float* __restrict__ rb)
{
    const int bx  = blockIdx.x;       // 0..127
    const int dir = bx >> 6;
    const int u0  = (bx & 63) * 8;
    const int tid = threadIdx.x;
    const int warp = tid >> 5, lane = tid & 31;
    const int gid = lane >> 2, tig = lane & 3;
    const int cg  = warp & 3;         // col group (n8)
    const int kh2 = warp >> 2;        // K half: 0 or 1
    const int dirbase = dir * 64;

    extern __shared__ char dsm[];
    unsigned short* h_s = (unsigned short*)dsm;    // [32][520] halves (LDSM conflict-free)
    float* red = (float*)(dsm + 66560);            // [4][32][8]

    // ---- resident W fragments: warp covers cols [cg*8, cg*8+8), K [kh2*256, +256) ----
    const float* __restrict__ rec = dir ? rb : rf;
    const int colc = cg * 8 + gid;
    const int colg = (colc & 3) * 512 + u0 + (colc >> 2);
    uint32_t bw_hi[16][2], bw_lo[16][2];
#pragma unroll
    for (int kc = 0; kc < 16; kc++) {
#pragma unroll
        for (int q = 0; q < 2; q++) {
            const int ka = kh2 * 256 + kc * 16 + 2 * tig + q * 8;
            float w0 = rec[(size_t)ka * 2048 + colg];
            float w1 = rec[(size_t)(ka + 1) * 2048 + colg];
            unsigned short h0 = f2bf(w0), h1 = f2bf(w1);
            unsigned short l0 = f2bf(w0 - bf2f(h0)), l1 = f2bf(w1 - bf2f(h1));
            bw_hi[kc][q] = (uint32_t)h0 | ((uint32_t)h1 << 16);
            bw_lo[kc][q] = (uint32_t)l0 | ((uint32_t)l1 << 16);
        }
    }

    // LDSM per-lane base addresses (bytes) for mi = 0,1
    const int lrow = lane & 15;
    const int lkof = ((lane >> 4) & 1) * 8;
    uint32_t ldsm_base[2];
#pragma unroll
    for (int mi = 0; mi < 2; mi++)
        ldsm_base[mi] = smem_u32(h_s) +
            2u * (uint32_t)((mi * 16 + lrow) * 520 + kh2 * 256 + lkof);

    // cell mapping for warps 0-3 (activation owners): 2 cells per lane
    const int uu = u0 + cg * 2 + (tig >> 1);
    const int bofs = (tig & 1) * 8;

    const float* __restrict__ xz = g_xz + (size_t)dir * (8192ull * 2048ull);
    unsigned short* hbase = g_h16 + dir * 32768;
    float c_st[2] = {0.f, 0.f};
    const int base = g_flags[bx * 32];
    __syncthreads();

    // prefetch xz for t=0 (warps 0-3)
    float z[2][4];
    if (kh2 == 0) {
        const int txi0 = dir ? 255 : 0;
#pragma unroll
        for (int mi = 0; mi < 2; mi++) {
            const int b = mi * 16 + gid + bofs;
            const float* slab = xz + ((size_t)txi0 * 32 + b) * 2048 + uu;
#pragma unroll
            for (int g = 0; g < 4; g++) z[mi][g] = slab[g * 512];
        }
    }

    for (int t = 0; t < 256; t++) {
        const int txi = dir ? (255 - t) : t;

        if (t > 0) {
            // stage h (bf16) into smem, coalesced uint4
            const uint4* h4 = (const uint4*)(hbase + ((t + 1) & 1) * 16384);
#pragma unroll
            for (int j = 0; j < 8; j++) {
                int i = tid + j * 256;
                uint4 v = __ldcg(&h4[i]);
                int b = i >> 6, kq = i & 63;
                *(uint4*)&h_s[b * 520 + kq * 8] = v;
            }
            __syncthreads();

            float c[2][4];
#pragma unroll
            for (int mi = 0; mi < 2; mi++)
#pragma unroll
                for (int q = 0; q < 4; q++) c[mi][q] = 0.f;

#pragma unroll
            for (int kc = 0; kc < 16; kc++) {
#pragma unroll
                for (int mi = 0; mi < 2; mi++) {
                    uint32_t af[4];
                    ldsm_x4(af, ldsm_base[mi] + kc * 32);
                    mma_bf16(c[mi], af, bw_hi[kc]);
                    mma_bf16(c[mi], af, bw_lo[kc]);
                }
            }

            // pair reduce: upper K-half warps publish, lower add
            if (kh2 == 1) {
                float* rp = red + (cg * 32 + lane) * 8;
                *(float4*)&rp[0] = make_float4(c[0][0], c[0][1], c[0][2], c[0][3]);
                *(float4*)&rp[4] = make_float4(c[1][0], c[1][1], c[1][2], c[1][3]);
            }
            __syncthreads();

            if (kh2 == 0) {
                const float* rp = red + (cg * 32 + lane) * 8;
                float4 p0 = *(const float4*)&rp[0];
                float4 p1 = *(const float4*)&rp[4];
                c[0][0] += p0.x; c[0][1] += p0.y; c[0][2] += p0.z; c[0][3] += p0.w;
                c[1][0] += p1.x; c[1][1] += p1.y; c[1][2] += p1.z; c[1][3] += p1.w;

                // shfl-gather: even tig -> gates of row r; odd tig -> gates of row r+8
#pragma unroll
                for (int mi = 0; mi < 2; mi++) {
                    float s0 = __shfl_xor_sync(0xffffffffu, c[mi][0], 1);
                    float s1 = __shfl_xor_sync(0xffffffffu, c[mi][1], 1);
                    float s2 = __shfl_xor_sync(0xffffffffu, c[mi][2], 1);
                    float s3 = __shfl_xor_sync(0xffffffffu, c[mi][3], 1);
                    if ((tig & 1) == 0) {
                        z[mi][0] += c[mi][0]; z[mi][1] += c[mi][1];
                        z[mi][2] += s0;       z[mi][3] += s1;
                    } else {
                        z[mi][0] += s2;       z[mi][1] += s3;
                        z[mi][2] += c[mi][2]; z[mi][3] += c[mi][3];
                    }
                }
            }
        }

        // activation + h publish (warps 0-3 only; 2 cells per lane)
        float hout[2];
        if (kh2 == 0) {
#pragma unroll
            for (int mi = 0; mi < 2; mi++) {
                float ig = fast_sigmoid(z[mi][0]);
                float fg = fast_sigmoid(z[mi][1]);
                float gg = fast_tanh(z[mi][2]);
                float og = fast_sigmoid(z[mi][3]);
                c_st[mi] = fmaf(fg, c_st[mi], ig * gg);
                hout[mi] = og * fast_tanh(c_st[mi]);
                if (t < 255) {
                    const int b = mi * 16 + gid + bofs;
                    hbase[(t & 1) * 16384 + b * 512 + uu] = f2bf(hout[mi]);
                }
            }
        }

        if (t < 255) {
            __threadfence();
            __syncthreads();
            if (tid == 0) g_flags[bx * 32] = base + t + 1;
        }

        // non-critical: output store + next-step xz prefetch (hidden under barrier wait)
        if (kh2 == 0) {
#pragma unroll
            for (int mi = 0; mi < 2; mi++) {
                const int b = mi * 16 + gid + bofs;
                g_hs[((size_t)b * 256 + txi) * 1024 + dir * 512 + uu] = hout[mi];
            }
            if (t < 255) {
                const int txn = dir ? (255 - (t + 1)) : (t + 1);
#pragma unroll
                for (int mi = 0; mi < 2; mi++) {
                    const int b = mi * 16 + gid + bofs;
                    const float* slab = xz + ((size_t)txn * 32 + b) * 2048 + uu;
#pragma unroll
                    for (int g = 0; g < 4; g++) z[mi][g] = slab[g * 512];
                }
            }
        }

        if (t < 255) {
            // acquire: poll on kh2=1 warps (tid 128..191), idle after partial publish
            if (tid >= 128 && tid < 192) {
                int spins = 0;
                const int target = base + t + 1;
                while (g_flags[(dirbase + (tid - 128)) * 32] < target) {
                    if (++spins > SPIN_CAP) break;
                }
            }
            __syncthreads();
            __threadfence();
        }
    }
}

// ================= K3: dense + SELU (2 rows per warp) ============================
__global__ __launch_bounds__(256) void dense_kernel(
    const float* __restrict__ W, const float* __restrict__ bias, float* __restrict__ logits)
{
    int wpair = (blockIdx.x * blockDim.x + threadIdx.x) >> 5;   // 0..4095
    int lane = threadIdx.x & 31;
    if (wpair >= 4096) return;
    const size_t r0 = (size_t)wpair * 2;
    const float4* h0 = (const float4*)(g_hs + r0 * 1024);
    const float4* h1 = (const float4*)(g_hs + (r0 + 1) * 1024);
    float acc0 = 0.f, acc1 = 0.f;
#pragma unroll 4
    for (int k4 = 0; k4 < 256; k4++) {
        float4 a = h0[k4];
        float4 b = h1[k4];
        int k = k4 * 4;
        if (lane < 25) {
            float w0 = W[(k + 0) * 25 + lane];
            float w1 = W[(k + 1) * 25 + lane];
            float w2 = W[(k + 2) * 25 + lane];
            float w3 = W[(k + 3) * 25 + lane];
            acc0 = fmaf(a.x, w0, acc0); acc1 = fmaf(b.x, w0, acc1);
            acc0 = fmaf(a.y, w1, acc0); acc1 = fmaf(b.y, w1, acc1);
            acc0 = fmaf(a.z, w2, acc0); acc1 = fmaf(b.z, w2, acc1);
            acc0 = fmaf(a.w, w3, acc0); acc1 = fmaf(b.w, w3, acc1);
        }
    }
    if (lane < 25) {
        float bi = bias[lane];
        float y0 = acc0 + bi, y1 = acc1 + bi;
        y0 = 1.0507009873554805f * (y0 > 0.f ? y0 : 1.6732632423543772f * (__expf(y0) - 1.f));
        y1 = 1.0507009873554805f * (y1 > 0.f ? y1 : 1.6732632423543772f * (__expf(y1) - 1.f));
        logits[r0 * 25 + lane] = y0;
        logits[(r0 + 1) * 25 + lane] = y1;
    }
}

// ================= K4: CRF NLL per batch (register alpha + shfl) =================
__global__ __launch_bounds__(32) void crf_kernel(
    const float* __restrict__ logits, const int* __restrict__ tags,
    const int* __restrict__ lens, const float* __restrict__ trans)
{
    const int b = blockIdx.x;
    const int j = threadIdx.x;
    __shared__ float tr[625];
    for (int i = j; i < 625; i += 32) tr[i] = trans[i];
    int len = lens[b];
    if (len < 1) len = 1;
    if (len > 256) len = 256;
    const float* lg = logits + (size_t)b * 256 * 25;
    __syncthreads();

    float a = (j < 25) ? lg[j] : -1e30f;
    for (int t = 1; t < 256; t++) {
        float m = -1e30f;
        float v[25];
#pragma unroll
        for (int i = 0; i < 25; i++) {
            v[i] = __shfl_sync(0xffffffffu, a, i) + tr[i * 25 + j];
            m = fmaxf(m, v[i]);
        }
        float s = 0.f;
#pragma unroll
        for (int i = 0; i < 25; i++) s += __expf(v[i] - m);
        float nv = m + __logf(s) + lg[t * 25 + j];
        if (j < 25 && t < len) a = nv;
    }

    float m = a;
#pragma unroll
    for (int o = 16; o > 0; o >>= 1) m = fmaxf(m, __shfl_xor_sync(0xffffffffu, m, o));
    float e = (j < 25) ? __expf(a - m) : 0.f;
#pragma unroll
    for (int o = 16; o > 0; o >>= 1) e += __shfl_xor_sync(0xffffffffu, e, o);
    float logz = m + __logf(e);

    const int* tg = tags + (size_t)b * 256;
    float us = 0.f, bs = 0.f;
    for (int t = j; t < 256; t += 32) {
        if (t < len) {
            us += lg[t * 25 + tg[t]];
            if (t >= 1) bs += tr[tg[t - 1] * 25 + tg[t]];
        }
    }
#pragma unroll
    for (int o = 16; o > 0; o >>= 1) {
        us += __shfl_xor_sync(0xffffffffu, us, o);
        bs += __shfl_xor_sync(0xffffffffu, bs, o);
    }
    if (j == 0) g_nll[b] = -(us + bs - logz);
}

// ================= K5: loss = mean(nll) =================
__global__ __launch_bounds__(32) void loss_kernel(float* __restrict__ out)
{
    float v = g_nll[threadIdx.x];
#pragma unroll
    for (int o = 16; o > 0; o >>= 1) v += __shfl_xor_sync(0xffffffffu, v, o);
    if (threadIdx.x == 0) out[0] = v * (1.f / 32.f);
}

// ================= launcher =================
extern "C" void kernel_launch(void* const* d_in, const int* in_sizes, int n_in,
                              void* d_out, int out_size)
{
    const float* x     = (const float*)d_in[0];
    const int*   tags  = (const int*)d_in[1];
    const int*   lens  = (const int*)d_in[2];
    const float* kf    = (const float*)d_in[3];
    const float* rf    = (const float*)d_in[4];
    const float* bf    = (const float*)d_in[5];
    const float* kb    = (const float*)d_in[6];
    const float* rb    = (const float*)d_in[7];
    const float* bb    = (const float*)d_in[8];
    const float* dw    = (const float*)d_in[9];
    const float* db    = (const float*)d_in[10];
    const float* trans = (const float*)d_in[11];
    float* out = (float*)d_out;

    (void)in_sizes; (void)n_in; (void)out_size;

    // K-1: profiling pad
    prof_pad_kernel<<<1, 32>>>();

    // K0a: pre-round x to tf32
    round_x_kernel<<<6144, 256>>>(x);

    // K0b: transpose + round input weights
    dim3 gt(64, 24, 2);
    transpose_w<<<gt, 256>>>(kf, kb);

    // K1: tf32 mma.sync input projections (pre-rounded operands, float4 stages)
    dim3 g1(32, 64);
    xz_gemm_mma<<<g1, 256>>>(bf, bb);

    // K2: persistent recurrence (proven R12/R15 config)
    const int k2_smem = 66560 + 4096;   // h_s [32][520] bf16 + red [4][32][8] f32
    cudaFuncSetAttribute(lstm_mma_kernel, cudaFuncAttributeMaxDynamicSharedMemorySize, k2_smem);
    lstm_mma_kernel<<<128, 256, k2_smem>>>(rf, rb);

    // K3: dense + SELU (2 rows per warp)
    dense_kernel<<<512, 256>>>(dw, db, out + 1);

    // K4: CRF per batch
    crf_kernel<<<32, 32>>>(out + 1, tags, lens, trans);

    // K5: mean loss
    loss_kernel<<<1, 32>>>(out);
}